// round 4
// baseline (speedup 1.0000x reference)
#include <cuda_runtime.h>
#include <cstdint>

#define LOG2E     1.4426950408889634f
#define TWO_LOG2E 2.8853900817779268f
#define GRU_CTAS  128

// ---------------- scratch (device globals: no allocation allowed) ----------
__device__ float    g_gi[2400 * 768];   // pre-GRU input gates  [t*8+n][768]
__device__ float    g_u2[1280 * 256];   // 2*log2e * (memory @ U^T)  [n*160+x][256]
__device__ float    g_w2[2400 * 256];   // 2*log2e * (outputs @ W^T) [n*300+t][256]
__device__ float    g_hb[2 * 8 * 256];  // ping-pong hidden state
__device__ unsigned g_flags[GRU_CTAS];  // per-CTA monotone step flags (NO atomics)

// ---------------- fast math ------------------------------------------------
__device__ __forceinline__ float ex2f_(float x) {
    float y; asm("ex2.approx.f32 %0, %1;" : "=f"(y) : "f"(x)); return y;
}
__device__ __forceinline__ float rcpf_(float x) {
    float y; asm("rcp.approx.f32 %0, %1;" : "=f"(y) : "f"(x)); return y;
}
__device__ __forceinline__ float sigmoidf_(float x) {
    return rcpf_(1.f + ex2f_(-x * LOG2E));
}
__device__ __forceinline__ float tanhf_(float x) {
    // tanh(x) = 1 - 2/(exp(2x)+1); exact at +-inf, ~1e-6 error
    return fmaf(-2.f, rcpf_(1.f + ex2f_(x * TWO_LOG2E)), 1.f);
}

// ---------------- kernel A: gi = inputs @ Wih^T + bih (+bhh for r,z) -------
// out rows indexed i = t*8 + n ; grid (150, 3), block 256
// bhh folded ONLY for gates r,z (jb<2); n-gate recurrent bias stays inside
// the reset product: n = tanh(i_n + r*(hdot + bhh_n)).
__global__ void gi_kernel(const float* __restrict__ inp,
                          const float* __restrict__ Wih,
                          const float* __restrict__ bih,
                          const float* __restrict__ bhh) {
    __shared__ float xs[16][128];
    int tid = threadIdx.x;
    int ib = blockIdx.x, jb = blockIdx.y;
    int j = jb * 256 + tid;

    for (int q = 0; q < 2; q++) {
        int f4 = tid + 256 * q;          // 0..511 float4 slots (16 rows * 32)
        int ii = f4 >> 5, pos = f4 & 31;
        int i = ib * 16 + ii;
        int t = i >> 3, n = i & 7;
        ((float4*)xs[ii])[pos] = ((const float4*)(inp + (n * 300 + t) * 128))[pos];
    }
    __syncthreads();

    float acc[16];
#pragma unroll
    for (int ii = 0; ii < 16; ii++) acc[ii] = 0.f;

    const float4* wr = (const float4*)(Wih + (size_t)j * 128);
    for (int k4 = 0; k4 < 32; k4++) {
        float4 w4 = __ldg(wr + k4);
#pragma unroll
        for (int ii = 0; ii < 16; ii++) {
            float4 xv = ((const float4*)xs[ii])[k4];
            acc[ii] = fmaf(w4.x, xv.x, acc[ii]);
            acc[ii] = fmaf(w4.y, xv.y, acc[ii]);
            acc[ii] = fmaf(w4.z, xv.z, acc[ii]);
            acc[ii] = fmaf(w4.w, xv.w, acc[ii]);
        }
    }
    float b = bih[j] + (jb < 2 ? bhh[j] : 0.f);
#pragma unroll
    for (int ii = 0; ii < 16; ii++)
        g_gi[(size_t)(ib * 16 + ii) * 768 + j] = acc[ii] + b;
}

// ---------------- shared 256-K GEMM body: out[i][j] = scale * A_i . B_j ----
__device__ __forceinline__ void gemm256_body(const float* __restrict__ A,
                                             const float* __restrict__ B,
                                             float* __restrict__ out,
                                             float scale) {
    __shared__ float xs[16][256];
    int tid = threadIdx.x, ib = blockIdx.x;
    for (int q = 0; q < 4; q++) {
        int f4 = tid + 256 * q;          // 0..1023 (16 rows * 64)
        int ii = f4 >> 6, pos = f4 & 63;
        ((float4*)xs[ii])[pos] = ((const float4*)(A + (size_t)(ib * 16 + ii) * 256))[pos];
    }
    __syncthreads();

    float acc[16];
#pragma unroll
    for (int ii = 0; ii < 16; ii++) acc[ii] = 0.f;

    const float4* br = (const float4*)(B + (size_t)tid * 256);
    for (int k4 = 0; k4 < 64; k4++) {
        float4 b4 = __ldg(br + k4);
#pragma unroll
        for (int ii = 0; ii < 16; ii++) {
            float4 xv = ((const float4*)xs[ii])[k4];
            acc[ii] = fmaf(b4.x, xv.x, acc[ii]);
            acc[ii] = fmaf(b4.y, xv.y, acc[ii]);
            acc[ii] = fmaf(b4.z, xv.z, acc[ii]);
            acc[ii] = fmaf(b4.w, xv.w, acc[ii]);
        }
    }
#pragma unroll
    for (int ii = 0; ii < 16; ii++)
        out[(size_t)(ib * 16 + ii) * 256 + tid] = scale * acc[ii];
}

__global__ void u_kernel(const float* __restrict__ mem, const float* __restrict__ U) {
    gemm256_body(mem, U, g_u2, TWO_LOG2E);   // pre-scale for tanh exponent
}
__global__ void w_kernel(const float* __restrict__ outp, const float* __restrict__ W) {
    gemm256_body(outp, W, g_w2, TWO_LOG2E);
}

// ---------------- persistent GRU kernel ------------------------------------
// 128 CTAs x 128 threads, 1 CTA/SM. CTA b owns hidden units {2b, 2b+1}.
// Thread (n = tid>>4, c = tid&15) handles k-chunk [16c,16c+16) for all 6
// gate-rows; Whh slice in REGISTERS; h LDG'd straight to registers each step.
// Grid barrier: per-CTA release STORE of step number (no atomics -> no L2
// atomic-ALU serialization); thread tid acquire-polls g_flags[tid].
__global__ void __launch_bounds__(128, 1)
gru_kernel(const float* __restrict__ h0, const float* __restrict__ Whh,
           const float* __restrict__ bhh,
           float* __restrict__ outp, float* __restrict__ hid) {
    __shared__ float hrow_s[8][16];     // h_old[n][e0&~15 ..] staging (intra-warp)

    int tid = threadIdx.x, bid = blockIdx.x;
    int e0 = 2 * bid;
    int n = tid >> 4, c = tid & 15;

    // Whh slice -> registers: rows lr = 2g+el  (R = g*256 + e0 + el), my k-chunk
    float4 w[6][4];
#pragma unroll
    for (int lr = 0; lr < 6; lr++) {
        int g = lr >> 1, el = lr & 1;
        const float4* wr = (const float4*)(Whh + (size_t)(g * 256 + e0 + el) * 256 + c * 16);
#pragma unroll
        for (int q = 0; q < 4; q++) w[lr][q] = __ldg(wr + q);
    }

    const int c_h = e0 >> 4;            // k-chunk containing e0, e0+1
    const int p0 = e0 & 15;

    const bool is_epi = (c < 2);        // lanes c=0,1 own hidden units e0+c
    const int eg = e0 + c;
    float bn = is_epi ? __ldg(bhh + 512 + eg) : 0.f;

    float ir = 0.f, iz = 0.f, inn = 0.f;
    if (is_epi) {
        const float* gib = g_gi + (size_t)(0 * 8 + n) * 768 + eg;
        ir = __ldg(gib); iz = __ldg(gib + 256); inn = __ldg(gib + 512);
    }

    const float* hsrc = h0 + n * 256 + c * 16;   // t=0 source
    unsigned* myflag = &g_flags[bid];
    unsigned* pollflag = &g_flags[tid];          // blockDim == GRU_CTAS

    for (int t = 0; t < 300; t++) {
        float4 h4[4];
#pragma unroll
        for (int q = 0; q < 4; q++) h4[q] = __ldcg((const float4*)hsrc + q);

        if (c == c_h) {
#pragma unroll
            for (int q = 0; q < 4; q++)
                *(float4*)&hrow_s[n][q * 4] = h4[q];
        }
        __syncwarp();                    // writer/reader share the warp

        float acc[6];
#pragma unroll
        for (int lr = 0; lr < 6; lr++) acc[lr] = 0.f;
#pragma unroll
        for (int lr = 0; lr < 6; lr++) {
#pragma unroll
            for (int q = 0; q < 4; q++) {
                acc[lr] = fmaf(w[lr][q].x, h4[q].x, acc[lr]);
                acc[lr] = fmaf(w[lr][q].y, h4[q].y, acc[lr]);
                acc[lr] = fmaf(w[lr][q].z, h4[q].z, acc[lr]);
                acc[lr] = fmaf(w[lr][q].w, h4[q].w, acc[lr]);
            }
        }
        // reduce across the 16-lane k-split (xor stays inside each half-warp)
#pragma unroll
        for (int o = 8; o >= 1; o >>= 1) {
#pragma unroll
            for (int lr = 0; lr < 6; lr++)
                acc[lr] += __shfl_xor_sync(0xffffffffu, acc[lr], o);
        }

        float hnew = 0.f;
        if (is_epi) {
            float gr = c ? acc[1] : acc[0];
            float gz = c ? acc[3] : acc[2];
            float gn = c ? acc[5] : acc[4];
            float r  = sigmoidf_(ir + gr);
            float z  = sigmoidf_(iz + gz);
            float nn = tanhf_(fmaf(r, gn + bn, inn));   // n = tanh(i_n + r*(hdot+bhh_n))
            float hold = hrow_s[n][p0 + c];
            hnew = fmaf(z, hold - nn, nn);
            __stcg(g_hb + ((t + 1) & 1) * 2048 + n * 256 + eg, hnew);
        }
        if (t == 299) {
            if (is_epi) {
                outp[(size_t)(n * 300 + t) * 256 + eg] = hnew;
                hid[n * 256 + eg] = hnew;
            }
            break;
        }

        // prefetch next step's input gates (latency hides under the barrier)
        if (is_epi) {
            const float* gib = g_gi + (size_t)((t + 1) * 8 + n) * 768 + eg;
            ir = __ldg(gib); iz = __ldg(gib + 256); inn = __ldg(gib + 512);
        }

        __syncthreads();                 // all h stores for step t done CTA-wide
        if (tid == 0) {                  // publish arrival: plain release STORE
            asm volatile("st.release.gpu.global.u32 [%0], %1;"
                         :: "l"(myflag), "r"((unsigned)(t + 1)) : "memory");
        }
        // outp store off the release critical path (drains during the poll)
        if (is_epi)
            outp[(size_t)(n * 300 + t) * 256 + eg] = hnew;

        // distributed observe: thread tid watches CTA tid's flag
        unsigned vv;
        do {
            asm volatile("ld.acquire.gpu.global.u32 %0, [%1];"
                         : "=r"(vv) : "l"(pollflag) : "memory");
        } while (vv < (unsigned)(t + 1));
        __syncthreads();

        hsrc = g_hb + ((t + 1) & 1) * 2048 + n * 256 + c * 16;
    }
}

// ---------------- flag cleanup (before gru: resets for every replay) -------
__global__ void cleanup_kernel() {
    unsigned i = threadIdx.x;
    if (i < GRU_CTAS) g_flags[i] = 0u;
}

// ---------------- attention: scores + softmax -------------------------------
// grid (30, 8) = (t-blocks of 10, n); block 160 (one thread per x)
__global__ void attn_kernel(const float* __restrict__ v, float* __restrict__ attn) {
    __shared__ float w2s[10 * 256];
    __shared__ float vs[256];
    __shared__ float red[8];

    int x = threadIdx.x;                 // 0..159
    int tb = blockIdx.x, n = blockIdx.y;
    int t0 = tb * 10;

    for (int i = x; i < 2560; i += 160)
        w2s[i] = g_w2[(size_t)(n * 300 + t0) * 256 + i];
    for (int i = x; i < 256; i += 160)
        vs[i] = v[i];
    __syncthreads();

    float S;
    {
        float s0 = 0.f, s1 = 0.f, s2 = 0.f, s3 = 0.f;
        for (int e = 0; e < 256; e += 4) {
            s0 += vs[e]; s1 += vs[e + 1]; s2 += vs[e + 2]; s3 += vs[e + 3];
        }
        S = (s0 + s1) + (s2 + s3);
    }

    float acc[10];
#pragma unroll
    for (int tt = 0; tt < 10; tt++) acc[tt] = 0.f;

    const float4* urow = (const float4*)(g_u2 + (size_t)(n * 160 + x) * 256);
    for (int e4 = 0; e4 < 64; e4++) {
        float4 u4 = __ldg(urow + e4);
#pragma unroll
        for (int j = 0; j < 4; j++) {
            float ue = (j == 0) ? u4.x : (j == 1) ? u4.y : (j == 2) ? u4.z : u4.w;
            int e = e4 * 4 + j;
            float ve = vs[e];
#pragma unroll
            for (int tt = 0; tt < 10; tt++) {
                float a = w2s[tt * 256 + e] + ue;      // already * 2*log2e
                float r = rcpf_(1.f + ex2f_(a));       // tanh = 1 - 2r
                acc[tt] = fmaf(ve, r, acc[tt]);
            }
        }
    }

    int lane = x & 31, wid = x >> 5;
    for (int tt = 0; tt < 10; tt++) {
        float sc = fmaf(-2.f, acc[tt], S);
        float m = sc;
#pragma unroll
        for (int o = 16; o > 0; o >>= 1)
            m = fmaxf(m, __shfl_xor_sync(0xffffffffu, m, o));
        if (lane == 0) red[wid] = m;
        __syncthreads();
        m = fmaxf(fmaxf(fmaxf(red[0], red[1]), fmaxf(red[2], red[3])), red[4]);

        float p = ex2f_((sc - m) * LOG2E);
        float s = p;
#pragma unroll
        for (int o = 16; o > 0; o >>= 1)
            s += __shfl_xor_sync(0xffffffffu, s, o);
        __syncthreads();
        if (lane == 0) red[wid] = s;
        __syncthreads();
        s = ((red[0] + red[1]) + (red[2] + red[3])) + red[4];

        attn[(size_t)(n * 300 + t0 + tt) * 160 + x] = p * rcpf_(s);
        __syncthreads();
    }
}

// ---------------- launcher ---------------------------------------------------
extern "C" void kernel_launch(void* const* d_in, const int* in_sizes, int n_in,
                              void* d_out, int out_size) {
    (void)in_sizes; (void)n_in; (void)out_size;
    const float* inputs = (const float*)d_in[0];
    const float* memory = (const float*)d_in[1];
    const float* h0     = (const float*)d_in[2];
    const float* Wih    = (const float*)d_in[3];
    const float* Whh    = (const float*)d_in[4];
    const float* bih    = (const float*)d_in[5];
    const float* bhh    = (const float*)d_in[6];
    const float* W      = (const float*)d_in[7];
    const float* U      = (const float*)d_in[8];
    const float* v      = (const float*)d_in[9];

    float* out     = (float*)d_out;
    float* attn    = out;                 // [8,300,160] = 384000
    float* outputs = out + 384000;        // [8,300,256] = 614400
    float* hidden  = out + 998400;        // [1,8,256]   = 2048

    gi_kernel<<<dim3(150, 3), 256>>>(inputs, Wih, bih, bhh);
    u_kernel<<<80, 256>>>(memory, U);
    cleanup_kernel<<<1, 128>>>();
    gru_kernel<<<GRU_CTAS, 128>>>(h0, Whh, bhh, outputs, hidden);
    w_kernel<<<150, 256>>>(outputs, W);
    attn_kernel<<<dim3(30, 8), 160>>>(v, attn);
}

// round 5
// speedup vs baseline: 1.2557x; 1.2557x over previous
#include <cuda_runtime.h>
#include <cstdint>

#define LOG2E     1.4426950408889634f
#define TWO_LOG2E 2.8853900817779268f
#define GRU_CTAS  128

// ---------------- scratch (device globals: no allocation allowed) ----------
__device__ float    g_gi[2400 * 768];   // pre-GRU input gates  [t*8+n][768]
__device__ float    g_u2[1280 * 256];   // 2*log2e * (memory @ U^T)  [n*160+x][256]
__device__ float    g_w2[2400 * 256];   // 2*log2e * (outputs @ W^T) [n*300+t][256]
__device__ float    g_hb[2 * 8 * 256];  // ping-pong hidden state
__device__ unsigned g_flags[GRU_CTAS];  // per-CTA monotone step flags (NO atomics)

// ---------------- fast math ------------------------------------------------
__device__ __forceinline__ float ex2f_(float x) {
    float y; asm("ex2.approx.f32 %0, %1;" : "=f"(y) : "f"(x)); return y;
}
__device__ __forceinline__ float rcpf_(float x) {
    float y; asm("rcp.approx.f32 %0, %1;" : "=f"(y) : "f"(x)); return y;
}
__device__ __forceinline__ float sigmoidf_(float x) {
    return rcpf_(1.f + ex2f_(-x * LOG2E));
}
__device__ __forceinline__ float tanhf_(float x) {
    // tanh(x) = 1 - 2/(exp(2x)+1); exact at +-inf, ~1e-6 error
    return fmaf(-2.f, rcpf_(1.f + ex2f_(x * TWO_LOG2E)), 1.f);
}

// ---------------- kernel A: gi = inputs @ Wih^T + bih (+bhh for r,z) -------
// out rows indexed i = t*8 + n ; grid (150, 3), block 256
// bhh folded ONLY for gates r,z (jb<2); n-gate recurrent bias stays inside
// the reset product: n = tanh(i_n + r*(hdot + bhh_n)).
__global__ void gi_kernel(const float* __restrict__ inp,
                          const float* __restrict__ Wih,
                          const float* __restrict__ bih,
                          const float* __restrict__ bhh) {
    __shared__ float xs[16][128];
    int tid = threadIdx.x;
    int ib = blockIdx.x, jb = blockIdx.y;
    int j = jb * 256 + tid;

    for (int q = 0; q < 2; q++) {
        int f4 = tid + 256 * q;          // 0..511 float4 slots (16 rows * 32)
        int ii = f4 >> 5, pos = f4 & 31;
        int i = ib * 16 + ii;
        int t = i >> 3, n = i & 7;
        ((float4*)xs[ii])[pos] = ((const float4*)(inp + (n * 300 + t) * 128))[pos];
    }
    __syncthreads();

    float acc[16];
#pragma unroll
    for (int ii = 0; ii < 16; ii++) acc[ii] = 0.f;

    const float4* wr = (const float4*)(Wih + (size_t)j * 128);
    for (int k4 = 0; k4 < 32; k4++) {
        float4 w4 = __ldg(wr + k4);
#pragma unroll
        for (int ii = 0; ii < 16; ii++) {
            float4 xv = ((const float4*)xs[ii])[k4];
            acc[ii] = fmaf(w4.x, xv.x, acc[ii]);
            acc[ii] = fmaf(w4.y, xv.y, acc[ii]);
            acc[ii] = fmaf(w4.z, xv.z, acc[ii]);
            acc[ii] = fmaf(w4.w, xv.w, acc[ii]);
        }
    }
    float b = bih[j] + (jb < 2 ? bhh[j] : 0.f);
#pragma unroll
    for (int ii = 0; ii < 16; ii++)
        g_gi[(size_t)(ib * 16 + ii) * 768 + j] = acc[ii] + b;
}

// ---------------- shared 256-K GEMM body: out[i][j] = scale * A_i . B_j ----
__device__ __forceinline__ void gemm256_body(const float* __restrict__ A,
                                             const float* __restrict__ B,
                                             float* __restrict__ out,
                                             float scale) {
    __shared__ float xs[16][256];
    int tid = threadIdx.x, ib = blockIdx.x;
    for (int q = 0; q < 4; q++) {
        int f4 = tid + 256 * q;          // 0..1023 (16 rows * 64)
        int ii = f4 >> 6, pos = f4 & 63;
        ((float4*)xs[ii])[pos] = ((const float4*)(A + (size_t)(ib * 16 + ii) * 256))[pos];
    }
    __syncthreads();

    float acc[16];
#pragma unroll
    for (int ii = 0; ii < 16; ii++) acc[ii] = 0.f;

    const float4* br = (const float4*)(B + (size_t)tid * 256);
    for (int k4 = 0; k4 < 64; k4++) {
        float4 b4 = __ldg(br + k4);
#pragma unroll
        for (int ii = 0; ii < 16; ii++) {
            float4 xv = ((const float4*)xs[ii])[k4];
            acc[ii] = fmaf(b4.x, xv.x, acc[ii]);
            acc[ii] = fmaf(b4.y, xv.y, acc[ii]);
            acc[ii] = fmaf(b4.z, xv.z, acc[ii]);
            acc[ii] = fmaf(b4.w, xv.w, acc[ii]);
        }
    }
#pragma unroll
    for (int ii = 0; ii < 16; ii++)
        out[(size_t)(ib * 16 + ii) * 256 + tid] = scale * acc[ii];
}

__global__ void u_kernel(const float* __restrict__ mem, const float* __restrict__ U) {
    gemm256_body(mem, U, g_u2, TWO_LOG2E);   // pre-scale for tanh exponent
}
__global__ void w_kernel(const float* __restrict__ outp, const float* __restrict__ W) {
    gemm256_body(outp, W, g_w2, TWO_LOG2E);
}

// ---------------- persistent GRU kernel ------------------------------------
// 128 CTAs x 128 threads, 1 CTA/SM. CTA b owns hidden units {2b, 2b+1}.
// Thread (n = tid>>4, c = tid&15) handles k-chunk [16c,16c+16) for all 6
// gate-rows; Whh slice in REGISTERS; h LDG'd straight to registers each step.
// Grid barrier: per-CTA release STORE of the step number; ONLY warp 0 of each
// CTA observes — lane L acquire-polls flags[4L..4L+4) with one v4 load; then
// __syncthreads releases the CTA. 4096 pollers grid-wide (vs 16K in R4).
__global__ void __launch_bounds__(128, 1)
gru_kernel(const float* __restrict__ h0, const float* __restrict__ Whh,
           const float* __restrict__ bhh,
           float* __restrict__ outp, float* __restrict__ hid) {
    __shared__ float hrow_s[8][16];     // h_old[n][e0&~15 ..] staging (intra-warp)

    int tid = threadIdx.x, bid = blockIdx.x;
    int e0 = 2 * bid;
    int n = tid >> 4, c = tid & 15;

    // Whh slice -> registers: rows lr = 2g+el  (R = g*256 + e0 + el), my k-chunk
    float4 w[6][4];
#pragma unroll
    for (int lr = 0; lr < 6; lr++) {
        int g = lr >> 1, el = lr & 1;
        const float4* wr = (const float4*)(Whh + (size_t)(g * 256 + e0 + el) * 256 + c * 16);
#pragma unroll
        for (int q = 0; q < 4; q++) w[lr][q] = __ldg(wr + q);
    }

    const int c_h = e0 >> 4;            // k-chunk containing e0, e0+1
    const int p0 = e0 & 15;

    const bool is_epi = (c < 2);        // lanes c=0,1 own hidden units e0+c
    const int eg = e0 + c;
    float bn = is_epi ? __ldg(bhh + 512 + eg) : 0.f;

    float ir = 0.f, iz = 0.f, inn = 0.f;
    if (is_epi) {
        const float* gib = g_gi + (size_t)(0 * 8 + n) * 768 + eg;
        ir = __ldg(gib); iz = __ldg(gib + 256); inn = __ldg(gib + 512);
    }

    const float* hsrc = h0 + n * 256 + c * 16;   // t=0 source
    unsigned* myflag = &g_flags[bid];
    const unsigned* sweep = &g_flags[(tid & 31) * 4];   // warp-0 lane quad

    for (int t = 0; t < 300; t++) {
        float4 h4[4];
#pragma unroll
        for (int q = 0; q < 4; q++) h4[q] = __ldcg((const float4*)hsrc + q);

        if (c == c_h) {
#pragma unroll
            for (int q = 0; q < 4; q++)
                *(float4*)&hrow_s[n][q * 4] = h4[q];
        }
        __syncwarp();                    // writer/reader share the warp

        float acc[6];
#pragma unroll
        for (int lr = 0; lr < 6; lr++) acc[lr] = 0.f;
#pragma unroll
        for (int lr = 0; lr < 6; lr++) {
#pragma unroll
            for (int q = 0; q < 4; q++) {
                acc[lr] = fmaf(w[lr][q].x, h4[q].x, acc[lr]);
                acc[lr] = fmaf(w[lr][q].y, h4[q].y, acc[lr]);
                acc[lr] = fmaf(w[lr][q].z, h4[q].z, acc[lr]);
                acc[lr] = fmaf(w[lr][q].w, h4[q].w, acc[lr]);
            }
        }
        // reduce across the 16-lane k-split (xor stays inside each half-warp)
#pragma unroll
        for (int o = 8; o >= 1; o >>= 1) {
#pragma unroll
            for (int lr = 0; lr < 6; lr++)
                acc[lr] += __shfl_xor_sync(0xffffffffu, acc[lr], o);
        }

        float hnew = 0.f;
        if (is_epi) {
            float gr = c ? acc[1] : acc[0];
            float gz = c ? acc[3] : acc[2];
            float gn = c ? acc[5] : acc[4];
            float r  = sigmoidf_(ir + gr);
            float z  = sigmoidf_(iz + gz);
            float nn = tanhf_(fmaf(r, gn + bn, inn));   // n = tanh(i_n + r*(hdot+bhh_n))
            float hold = hrow_s[n][p0 + c];
            hnew = fmaf(z, hold - nn, nn);
            __stcg(g_hb + ((t + 1) & 1) * 2048 + n * 256 + eg, hnew);
        }
        if (t == 299) {
            if (is_epi) {
                outp[(size_t)(n * 300 + t) * 256 + eg] = hnew;
                hid[n * 256 + eg] = hnew;
            }
            break;
        }

        // prefetch next step's input gates (latency hides under the barrier)
        if (is_epi) {
            const float* gib = g_gi + (size_t)((t + 1) * 8 + n) * 768 + eg;
            ir = __ldg(gib); iz = __ldg(gib + 256); inn = __ldg(gib + 512);
        }

        __syncthreads();                 // all h stores for step t done CTA-wide
        if (tid == 0) {                  // publish arrival: plain release STORE
            asm volatile("st.release.gpu.global.u32 [%0], %1;"
                         :: "l"(myflag), "r"((unsigned)(t + 1)) : "memory");
        }
        // outp store off the release critical path (drains during the poll)
        if (is_epi)
            outp[(size_t)(n * 300 + t) * 256 + eg] = hnew;

        // warp-0 sweep: lane L acquire-polls its 4 flags with ONE v4 load
        if (tid < 32) {
            unsigned s = (unsigned)(t + 1);
            unsigned f0, f1, f2, f3;
            do {
                asm volatile("ld.acquire.gpu.global.v4.u32 {%0,%1,%2,%3}, [%4];"
                             : "=r"(f0), "=r"(f1), "=r"(f2), "=r"(f3)
                             : "l"(sweep) : "memory");
            } while (f0 < s || f1 < s || f2 < s || f3 < s);
        }
        __syncthreads();                 // release whole CTA past the barrier

        hsrc = g_hb + ((t + 1) & 1) * 2048 + n * 256 + c * 16;
    }
}

// ---------------- flag cleanup (before gru: resets for every replay) -------
__global__ void cleanup_kernel() {
    unsigned i = threadIdx.x;
    if (i < GRU_CTAS) g_flags[i] = 0u;
}

// ---------------- attention: scores + softmax -------------------------------
// grid (30, 8) = (t-blocks of 10, n); block 160 (one thread per x)
__global__ void attn_kernel(const float* __restrict__ v, float* __restrict__ attn) {
    __shared__ float w2s[10 * 256];
    __shared__ float vs[256];
    __shared__ float red[8];

    int x = threadIdx.x;                 // 0..159
    int tb = blockIdx.x, n = blockIdx.y;
    int t0 = tb * 10;

    for (int i = x; i < 2560; i += 160)
        w2s[i] = g_w2[(size_t)(n * 300 + t0) * 256 + i];
    for (int i = x; i < 256; i += 160)
        vs[i] = v[i];
    __syncthreads();

    float S;
    {
        float s0 = 0.f, s1 = 0.f, s2 = 0.f, s3 = 0.f;
        for (int e = 0; e < 256; e += 4) {
            s0 += vs[e]; s1 += vs[e + 1]; s2 += vs[e + 2]; s3 += vs[e + 3];
        }
        S = (s0 + s1) + (s2 + s3);
    }

    float acc[10];
#pragma unroll
    for (int tt = 0; tt < 10; tt++) acc[tt] = 0.f;

    const float4* urow = (const float4*)(g_u2 + (size_t)(n * 160 + x) * 256);
    for (int e4 = 0; e4 < 64; e4++) {
        float4 u4 = __ldg(urow + e4);
#pragma unroll
        for (int j = 0; j < 4; j++) {
            float ue = (j == 0) ? u4.x : (j == 1) ? u4.y : (j == 2) ? u4.z : u4.w;
            int e = e4 * 4 + j;
            float ve = vs[e];
#pragma unroll
            for (int tt = 0; tt < 10; tt++) {
                float a = w2s[tt * 256 + e] + ue;      // already * 2*log2e
                float r = rcpf_(1.f + ex2f_(a));       // tanh = 1 - 2r
                acc[tt] = fmaf(ve, r, acc[tt]);
            }
        }
    }

    int lane = x & 31, wid = x >> 5;
    for (int tt = 0; tt < 10; tt++) {
        float sc = fmaf(-2.f, acc[tt], S);
        float m = sc;
#pragma unroll
        for (int o = 16; o > 0; o >>= 1)
            m = fmaxf(m, __shfl_xor_sync(0xffffffffu, m, o));
        if (lane == 0) red[wid] = m;
        __syncthreads();
        m = fmaxf(fmaxf(fmaxf(red[0], red[1]), fmaxf(red[2], red[3])), red[4]);

        float p = ex2f_((sc - m) * LOG2E);
        float s = p;
#pragma unroll
        for (int o = 16; o > 0; o >>= 1)
            s += __shfl_xor_sync(0xffffffffu, s, o);
        __syncthreads();
        if (lane == 0) red[wid] = s;
        __syncthreads();
        s = ((red[0] + red[1]) + (red[2] + red[3])) + red[4];

        attn[(size_t)(n * 300 + t0 + tt) * 160 + x] = p * rcpf_(s);
        __syncthreads();
    }
}

// ---------------- launcher ---------------------------------------------------
extern "C" void kernel_launch(void* const* d_in, const int* in_sizes, int n_in,
                              void* d_out, int out_size) {
    (void)in_sizes; (void)n_in; (void)out_size;
    const float* inputs = (const float*)d_in[0];
    const float* memory = (const float*)d_in[1];
    const float* h0     = (const float*)d_in[2];
    const float* Wih    = (const float*)d_in[3];
    const float* Whh    = (const float*)d_in[4];
    const float* bih    = (const float*)d_in[5];
    const float* bhh    = (const float*)d_in[6];
    const float* W      = (const float*)d_in[7];
    const float* U      = (const float*)d_in[8];
    const float* v      = (const float*)d_in[9];

    float* out     = (float*)d_out;
    float* attn    = out;                 // [8,300,160] = 384000
    float* outputs = out + 384000;        // [8,300,256] = 614400
    float* hidden  = out + 998400;        // [1,8,256]   = 2048

    gi_kernel<<<dim3(150, 3), 256>>>(inputs, Wih, bih, bhh);
    u_kernel<<<80, 256>>>(memory, U);
    cleanup_kernel<<<1, 128>>>();
    gru_kernel<<<GRU_CTAS, 128>>>(h0, Whh, bhh, outputs, hidden);
    w_kernel<<<150, 256>>>(outputs, W);
    attn_kernel<<<dim3(30, 8), 160>>>(v, attn);
}

// round 6
// speedup vs baseline: 3.0520x; 2.4306x over previous
#include <cuda_runtime.h>
#include <cstdint>

#define LOG2E     1.4426950408889634f
#define TWO_LOG2E 2.8853900817779268f

// ---------------- scratch (device globals: no allocation allowed) ----------
__device__ float g_gi[2400 * 768];   // pre-GRU input gates  [t*8+n][768]
__device__ float g_u2[1280 * 256];   // 2*log2e * (memory @ U^T)  [n*160+x][256]
__device__ float g_w2[2400 * 256];   // 2*log2e * (outputs @ W^T) [n*300+t][256]

// ---------------- fast math ------------------------------------------------
__device__ __forceinline__ float ex2f_(float x) {
    float y; asm("ex2.approx.f32 %0, %1;" : "=f"(y) : "f"(x)); return y;
}
__device__ __forceinline__ float rcpf_(float x) {
    float y; asm("rcp.approx.f32 %0, %1;" : "=f"(y) : "f"(x)); return y;
}
__device__ __forceinline__ float sigmoidf_(float x) {
    return rcpf_(1.f + ex2f_(-x * LOG2E));
}
__device__ __forceinline__ float tanhf_(float x) {
    return fmaf(-2.f, rcpf_(1.f + ex2f_(x * TWO_LOG2E)), 1.f);
}
__device__ __forceinline__ unsigned smem_u32_(const void* p) {
    unsigned a;
    asm("{ .reg .u64 t; cvta.to.shared.u64 t, %1; cvt.u32.u64 %0, t; }"
        : "=r"(a) : "l"(p));
    return a;
}

// ---------------- kernel A: gi = inputs @ Wih^T + bih (+bhh for r,z) -------
__global__ void gi_kernel(const float* __restrict__ inp,
                          const float* __restrict__ Wih,
                          const float* __restrict__ bih,
                          const float* __restrict__ bhh) {
    __shared__ float xs[16][128];
    int tid = threadIdx.x;
    int ib = blockIdx.x, jb = blockIdx.y;
    int j = jb * 256 + tid;

    for (int q = 0; q < 2; q++) {
        int f4 = tid + 256 * q;
        int ii = f4 >> 5, pos = f4 & 31;
        int i = ib * 16 + ii;
        int t = i >> 3, n = i & 7;
        ((float4*)xs[ii])[pos] = ((const float4*)(inp + (n * 300 + t) * 128))[pos];
    }
    __syncthreads();

    float acc[16];
#pragma unroll
    for (int ii = 0; ii < 16; ii++) acc[ii] = 0.f;

    const float4* wr = (const float4*)(Wih + (size_t)j * 128);
    for (int k4 = 0; k4 < 32; k4++) {
        float4 w4 = __ldg(wr + k4);
#pragma unroll
        for (int ii = 0; ii < 16; ii++) {
            float4 xv = ((const float4*)xs[ii])[k4];
            acc[ii] = fmaf(w4.x, xv.x, acc[ii]);
            acc[ii] = fmaf(w4.y, xv.y, acc[ii]);
            acc[ii] = fmaf(w4.z, xv.z, acc[ii]);
            acc[ii] = fmaf(w4.w, xv.w, acc[ii]);
        }
    }
    float b = bih[j] + (jb < 2 ? bhh[j] : 0.f);
#pragma unroll
    for (int ii = 0; ii < 16; ii++)
        g_gi[(size_t)(ib * 16 + ii) * 768 + j] = acc[ii] + b;
}

// ---------------- shared 256-K GEMM body ------------------------------------
__device__ __forceinline__ void gemm256_body(const float* __restrict__ A,
                                             const float* __restrict__ B,
                                             float* __restrict__ out,
                                             float scale) {
    __shared__ float xs[16][256];
    int tid = threadIdx.x, ib = blockIdx.x;
    for (int q = 0; q < 4; q++) {
        int f4 = tid + 256 * q;
        int ii = f4 >> 6, pos = f4 & 63;
        ((float4*)xs[ii])[pos] = ((const float4*)(A + (size_t)(ib * 16 + ii) * 256))[pos];
    }
    __syncthreads();

    float acc[16];
#pragma unroll
    for (int ii = 0; ii < 16; ii++) acc[ii] = 0.f;

    const float4* br = (const float4*)(B + (size_t)tid * 256);
    for (int k4 = 0; k4 < 64; k4++) {
        float4 b4 = __ldg(br + k4);
#pragma unroll
        for (int ii = 0; ii < 16; ii++) {
            float4 xv = ((const float4*)xs[ii])[k4];
            acc[ii] = fmaf(b4.x, xv.x, acc[ii]);
            acc[ii] = fmaf(b4.y, xv.y, acc[ii]);
            acc[ii] = fmaf(b4.z, xv.z, acc[ii]);
            acc[ii] = fmaf(b4.w, xv.w, acc[ii]);
        }
    }
#pragma unroll
    for (int ii = 0; ii < 16; ii++)
        out[(size_t)(ib * 16 + ii) * 256 + tid] = scale * acc[ii];
}

__global__ void u_kernel(const float* __restrict__ mem, const float* __restrict__ U) {
    gemm256_body(mem, U, g_u2, TWO_LOG2E);
}
__global__ void w_kernel(const float* __restrict__ outp, const float* __restrict__ W) {
    gemm256_body(outp, W, g_w2, TWO_LOG2E);
}

// ---------------- GRU: one 8-CTA cluster per batch; DSMEM h-exchange -------
// 64 CTAs x 256 threads, __cluster_dims__(8). Cluster k = batch n = bid>>3.
// CTA rank r owns units e in [32r, 32r+32). Thread t: u = t>>3 (unit),
// c = t&7 (k-chunk of 32). Whh slice in registers (24 float4). h in
// double-buffered smem; after each step each CTA pushes its 32 hnew floats
// into ALL 8 peers' hbuf via st.shared::cluster; step barrier =
// barrier.cluster.arrive/wait (release/acquire). No L2 flags at all.
__global__ void __launch_bounds__(256, 1) __cluster_dims__(8, 1, 1)
gru_kernel(const float* __restrict__ h0, const float* __restrict__ Whh,
           const float* __restrict__ bhh,
           float* __restrict__ outp, float* __restrict__ hid) {
    __shared__ float hbuf[2][256];
    __shared__ float stg[32];

    int tid = threadIdx.x;
    int n = blockIdx.x >> 3;
    unsigned r;
    asm("mov.u32 %0, %%cluster_ctarank;" : "=r"(r));

    int u = tid >> 3, c = tid & 7;      // unit within CTA, k-chunk

    // Whh rows for gates r,z,n of unit e=32r+u, k-cols [32c, 32c+32)
    float4 w0[8], w1[8], w2[8];
    {
        int e = 32 * (int)r + u;
        const float4* r0 = (const float4*)(Whh + (size_t)(e)        * 256 + c * 32);
        const float4* r1 = (const float4*)(Whh + (size_t)(256 + e)  * 256 + c * 32);
        const float4* r2 = (const float4*)(Whh + (size_t)(512 + e)  * 256 + c * 32);
#pragma unroll
        for (int q = 0; q < 8; q++) { w0[q] = __ldg(r0 + q); w1[q] = __ldg(r1 + q); w2[q] = __ldg(r2 + q); }
    }

    const bool is_epi = (c == 0);
    const int eg = 32 * (int)r + u;
    float bn = is_epi ? __ldg(bhh + 512 + eg) : 0.f;

    float ir = 0.f, iz = 0.f, inn = 0.f;
    if (is_epi) {
        const float* gib = g_gi + (size_t)n * 768 + eg;   // t = 0
        ir = __ldg(gib); iz = __ldg(gib + 256); inn = __ldg(gib + 512);
    }

    // initial h0 into buffer 0 (own full copy; no cross-CTA dependency)
    hbuf[0][tid] = h0[n * 256 + tid];
    __syncthreads();

    // pre-mapa'd peer addresses for both buffers (pusher threads 0..7)
    unsigned dst0 = 0, dst1 = 0;
    if (tid < 8) {
        unsigned l0 = smem_u32_(&hbuf[0][0]) + r * 128;   // our 32-unit slot
        unsigned l1 = smem_u32_(&hbuf[1][0]) + r * 128;
        asm("mapa.shared::cluster.u32 %0, %1, %2;" : "=r"(dst0) : "r"(l0), "r"((unsigned)tid));
        asm("mapa.shared::cluster.u32 %0, %1, %2;" : "=r"(dst1) : "r"(l1), "r"((unsigned)tid));
    }

    for (int t = 0; t < 300; t++) {
        const float* hb = &hbuf[t & 1][c * 32];
        float a0 = 0.f, a1 = 0.f, a2 = 0.f;
#pragma unroll
        for (int q = 0; q < 8; q++) {
            float4 h4 = *(const float4*)(hb + q * 4);
            a0 = fmaf(w0[q].x, h4.x, a0); a1 = fmaf(w1[q].x, h4.x, a1); a2 = fmaf(w2[q].x, h4.x, a2);
            a0 = fmaf(w0[q].y, h4.y, a0); a1 = fmaf(w1[q].y, h4.y, a1); a2 = fmaf(w2[q].y, h4.y, a2);
            a0 = fmaf(w0[q].z, h4.z, a0); a1 = fmaf(w1[q].z, h4.z, a1); a2 = fmaf(w2[q].z, h4.z, a2);
            a0 = fmaf(w0[q].w, h4.w, a0); a1 = fmaf(w1[q].w, h4.w, a1); a2 = fmaf(w2[q].w, h4.w, a2);
        }
        // reduce across the 8-lane k-split
#pragma unroll
        for (int o = 4; o >= 1; o >>= 1) {
            a0 += __shfl_xor_sync(0xffffffffu, a0, o);
            a1 += __shfl_xor_sync(0xffffffffu, a1, o);
            a2 += __shfl_xor_sync(0xffffffffu, a2, o);
        }

        float hnew = 0.f;
        if (is_epi) {
            float rg = sigmoidf_(ir + a0);
            float zg = sigmoidf_(iz + a1);
            float ng = tanhf_(fmaf(rg, a2 + bn, inn));   // n = tanh(i_n + r*(hdot+bhh_n))
            float hold = hbuf[t & 1][eg];
            hnew = fmaf(zg, hold - ng, ng);
            stg[u] = hnew;
            outp[(size_t)(n * 300 + t) * 256 + eg] = hnew;
        }
        if (t == 299) {
            if (is_epi) hid[n * 256 + eg] = hnew;
            break;
        }
        __syncthreads();                 // stg complete; hbuf[t&1] reads done

        // push our 32 hnew floats (128B) into peer tid's hbuf[(t+1)&1]
        if (tid < 8) {
            unsigned dst = ((t + 1) & 1) ? dst1 : dst0;
#pragma unroll
            for (int q = 0; q < 8; q++) {
                float4 v = *(const float4*)(&stg[q * 4]);
                asm volatile("st.shared::cluster.v4.b32 [%0], {%1,%2,%3,%4};"
                             :: "r"(dst + q * 16),
                                "r"(__float_as_uint(v.x)), "r"(__float_as_uint(v.y)),
                                "r"(__float_as_uint(v.z)), "r"(__float_as_uint(v.w))
                             : "memory");
            }
        }
        asm volatile("barrier.cluster.arrive.aligned;" ::: "memory");  // release

        // prefetch next step's input gates under the barrier
        if (is_epi) {
            const float* gib = g_gi + (size_t)((t + 1) * 8 + n) * 768 + eg;
            ir = __ldg(gib); iz = __ldg(gib + 256); inn = __ldg(gib + 512);
        }

        asm volatile("barrier.cluster.wait.aligned;" ::: "memory");    // acquire
    }
}

// ---------------- attention: scores + softmax -------------------------------
__global__ void attn_kernel(const float* __restrict__ v, float* __restrict__ attn) {
    __shared__ float w2s[10 * 256];
    __shared__ float vs[256];
    __shared__ float red[8];

    int x = threadIdx.x;                 // 0..159
    int tb = blockIdx.x, n = blockIdx.y;
    int t0 = tb * 10;

    for (int i = x; i < 2560; i += 160)
        w2s[i] = g_w2[(size_t)(n * 300 + t0) * 256 + i];
    for (int i = x; i < 256; i += 160)
        vs[i] = v[i];
    __syncthreads();

    float S;
    {
        float s0 = 0.f, s1 = 0.f, s2 = 0.f, s3 = 0.f;
        for (int e = 0; e < 256; e += 4) {
            s0 += vs[e]; s1 += vs[e + 1]; s2 += vs[e + 2]; s3 += vs[e + 3];
        }
        S = (s0 + s1) + (s2 + s3);
    }

    float acc[10];
#pragma unroll
    for (int tt = 0; tt < 10; tt++) acc[tt] = 0.f;

    const float4* urow = (const float4*)(g_u2 + (size_t)(n * 160 + x) * 256);
    for (int e4 = 0; e4 < 64; e4++) {
        float4 u4 = __ldg(urow + e4);
#pragma unroll
        for (int j = 0; j < 4; j++) {
            float ue = (j == 0) ? u4.x : (j == 1) ? u4.y : (j == 2) ? u4.z : u4.w;
            int e = e4 * 4 + j;
            float ve = vs[e];
#pragma unroll
            for (int tt = 0; tt < 10; tt++) {
                float a = w2s[tt * 256 + e] + ue;      // already * 2*log2e
                float r = rcpf_(1.f + ex2f_(a));       // tanh = 1 - 2r
                acc[tt] = fmaf(ve, r, acc[tt]);
            }
        }
    }

    int lane = x & 31, wid = x >> 5;
    for (int tt = 0; tt < 10; tt++) {
        float sc = fmaf(-2.f, acc[tt], S);
        float m = sc;
#pragma unroll
        for (int o = 16; o > 0; o >>= 1)
            m = fmaxf(m, __shfl_xor_sync(0xffffffffu, m, o));
        if (lane == 0) red[wid] = m;
        __syncthreads();
        m = fmaxf(fmaxf(fmaxf(red[0], red[1]), fmaxf(red[2], red[3])), red[4]);

        float p = ex2f_((sc - m) * LOG2E);
        float s = p;
#pragma unroll
        for (int o = 16; o > 0; o >>= 1)
            s += __shfl_xor_sync(0xffffffffu, s, o);
        __syncthreads();
        if (lane == 0) red[wid] = s;
        __syncthreads();
        s = ((red[0] + red[1]) + (red[2] + red[3])) + red[4];

        attn[(size_t)(n * 300 + t0 + tt) * 160 + x] = p * rcpf_(s);
        __syncthreads();
    }
}

// ---------------- launcher ---------------------------------------------------
extern "C" void kernel_launch(void* const* d_in, const int* in_sizes, int n_in,
                              void* d_out, int out_size) {
    (void)in_sizes; (void)n_in; (void)out_size;
    const float* inputs = (const float*)d_in[0];
    const float* memory = (const float*)d_in[1];
    const float* h0     = (const float*)d_in[2];
    const float* Wih    = (const float*)d_in[3];
    const float* Whh    = (const float*)d_in[4];
    const float* bih    = (const float*)d_in[5];
    const float* bhh    = (const float*)d_in[6];
    const float* W      = (const float*)d_in[7];
    const float* U      = (const float*)d_in[8];
    const float* v      = (const float*)d_in[9];

    float* out     = (float*)d_out;
    float* attn    = out;                 // [8,300,160] = 384000
    float* outputs = out + 384000;        // [8,300,256] = 614400
    float* hidden  = out + 998400;        // [1,8,256]   = 2048

    gi_kernel<<<dim3(150, 3), 256>>>(inputs, Wih, bih, bhh);
    u_kernel<<<80, 256>>>(memory, U);
    gru_kernel<<<64, 256>>>(h0, Whh, bhh, outputs, hidden);
    w_kernel<<<150, 256>>>(outputs, W);
    attn_kernel<<<dim3(30, 8), 160>>>(v, attn);
}

// round 7
// speedup vs baseline: 3.5562x; 1.1652x over previous
#include <cuda_runtime.h>
#include <cstdint>

#define LOG2E     1.4426950408889634f
#define TWO_LOG2E 2.8853900817779268f

// ---------------- scratch (device globals: no allocation allowed) ----------
__device__ float g_gi[2400 * 768];   // pre-GRU input gates  [t*8+n][768]
__device__ float g_u2[1280 * 256];   // 2*log2e * (memory @ U^T)  [n*160+x][256]
__device__ float g_w2[2400 * 256];   // 2*log2e * (outputs @ W^T) [n*300+t][256]

// ---------------- fast math ------------------------------------------------
__device__ __forceinline__ float ex2f_(float x) {
    float y; asm("ex2.approx.f32 %0, %1;" : "=f"(y) : "f"(x)); return y;
}
__device__ __forceinline__ float rcpf_(float x) {
    float y; asm("rcp.approx.f32 %0, %1;" : "=f"(y) : "f"(x)); return y;
}
__device__ __forceinline__ float sigmoidf_(float x) {
    return rcpf_(1.f + ex2f_(-x * LOG2E));
}
__device__ __forceinline__ float tanhf_(float x) {
    return fmaf(-2.f, rcpf_(1.f + ex2f_(x * TWO_LOG2E)), 1.f);
}
__device__ __forceinline__ unsigned smem_u32_(const void* p) {
    unsigned a;
    asm("{ .reg .u64 t; cvta.to.shared.u64 t, %1; cvt.u32.u64 %0, t; }"
        : "=r"(a) : "l"(p));
    return a;
}
__device__ __forceinline__ unsigned long long fma2_(unsigned long long a,
                                                    unsigned long long b,
                                                    unsigned long long c) {
    unsigned long long d;
    asm("fma.rn.f32x2 %0, %1, %2, %3;" : "=l"(d) : "l"(a), "l"(b), "l"(c));
    return d;
}

// ---------------- kernel A: gi = inputs @ Wih^T + bih (+bhh for r,z) -------
__global__ void gi_kernel(const float* __restrict__ inp,
                          const float* __restrict__ Wih,
                          const float* __restrict__ bih,
                          const float* __restrict__ bhh) {
    __shared__ float xs[16][128];
    int tid = threadIdx.x;
    int ib = blockIdx.x, jb = blockIdx.y;
    int j = jb * 256 + tid;

    for (int q = 0; q < 2; q++) {
        int f4 = tid + 256 * q;
        int ii = f4 >> 5, pos = f4 & 31;
        int i = ib * 16 + ii;
        int t = i >> 3, n = i & 7;
        ((float4*)xs[ii])[pos] = ((const float4*)(inp + (n * 300 + t) * 128))[pos];
    }
    __syncthreads();

    float acc[16];
#pragma unroll
    for (int ii = 0; ii < 16; ii++) acc[ii] = 0.f;

    const float4* wr = (const float4*)(Wih + (size_t)j * 128);
    for (int k4 = 0; k4 < 32; k4++) {
        float4 w4 = __ldg(wr + k4);
#pragma unroll
        for (int ii = 0; ii < 16; ii++) {
            float4 xv = ((const float4*)xs[ii])[k4];
            acc[ii] = fmaf(w4.x, xv.x, acc[ii]);
            acc[ii] = fmaf(w4.y, xv.y, acc[ii]);
            acc[ii] = fmaf(w4.z, xv.z, acc[ii]);
            acc[ii] = fmaf(w4.w, xv.w, acc[ii]);
        }
    }
    float b = bih[j] + (jb < 2 ? bhh[j] : 0.f);
#pragma unroll
    for (int ii = 0; ii < 16; ii++)
        g_gi[(size_t)(ib * 16 + ii) * 768 + j] = acc[ii] + b;
}

// ---------------- shared 256-K GEMM body ------------------------------------
__device__ __forceinline__ void gemm256_body(const float* __restrict__ A,
                                             const float* __restrict__ B,
                                             float* __restrict__ out,
                                             float scale) {
    __shared__ float xs[16][256];
    int tid = threadIdx.x, ib = blockIdx.x;
    for (int q = 0; q < 4; q++) {
        int f4 = tid + 256 * q;
        int ii = f4 >> 6, pos = f4 & 63;
        ((float4*)xs[ii])[pos] = ((const float4*)(A + (size_t)(ib * 16 + ii) * 256))[pos];
    }
    __syncthreads();

    float acc[16];
#pragma unroll
    for (int ii = 0; ii < 16; ii++) acc[ii] = 0.f;

    const float4* br = (const float4*)(B + (size_t)tid * 256);
    for (int k4 = 0; k4 < 64; k4++) {
        float4 b4 = __ldg(br + k4);
#pragma unroll
        for (int ii = 0; ii < 16; ii++) {
            float4 xv = ((const float4*)xs[ii])[k4];
            acc[ii] = fmaf(b4.x, xv.x, acc[ii]);
            acc[ii] = fmaf(b4.y, xv.y, acc[ii]);
            acc[ii] = fmaf(b4.z, xv.z, acc[ii]);
            acc[ii] = fmaf(b4.w, xv.w, acc[ii]);
        }
    }
#pragma unroll
    for (int ii = 0; ii < 16; ii++)
        out[(size_t)(ib * 16 + ii) * 256 + tid] = scale * acc[ii];
}

__global__ void u_kernel(const float* __restrict__ mem, const float* __restrict__ U) {
    gemm256_body(mem, U, g_u2, TWO_LOG2E);
}
__global__ void w_kernel(const float* __restrict__ outp, const float* __restrict__ W) {
    gemm256_body(outp, W, g_w2, TWO_LOG2E);
}

// ---------------- GRU: 8-CTA cluster per batch; st.async + mbarrier --------
// CTA rank r owns units [32r, 32r+32). Thread t: u = t>>3, c = t&7 (k-chunk
// of 32). Whh in registers as f32x2 pairs. Per step, owner threads (c==0)
// st.async their hnew float into all 8 CTAs' hbuf[next] with complete_tx to
// each CTA's mbar[next]; consumers try_wait their LOCAL mbarrier. No cluster
// barrier, no __syncthreads in the loop (ordering via data deps + mbarrier).
__global__ void __launch_bounds__(256, 1) __cluster_dims__(8, 1, 1)
gru_kernel(const float* __restrict__ h0, const float* __restrict__ Whh,
           const float* __restrict__ bhh,
           float* __restrict__ outp, float* __restrict__ hid) {
    __shared__ __align__(16) float hbuf[2][256];          // 1024B per buffer
    __shared__ __align__(8)  unsigned long long mbar[2];

    int tid = threadIdx.x;
    int n = blockIdx.x >> 3;
    unsigned r;
    asm("mov.u32 %0, %%cluster_ctarank;" : "=r"(r));
    int u = tid >> 3, c = tid & 7;
    const int eg = 32 * (int)r + u;

    // init mbarriers (count=1: the expect_tx arrive), then cluster-wide sync
    if (tid == 0) {
        unsigned m0 = smem_u32_(&mbar[0]);
        asm volatile("mbarrier.init.shared.b64 [%0], 1;" :: "r"(m0) : "memory");
        asm volatile("mbarrier.init.shared.b64 [%0], 1;" :: "r"(m0 + 8) : "memory");
    }
    hbuf[0][tid] = h0[n * 256 + tid];
    __syncthreads();
    asm volatile("barrier.cluster.arrive.aligned;" ::: "memory");

    // Whh rows (gates r,z,n) for unit eg, k-cols [32c,32c+32), as f32x2 pairs
    unsigned long long w0[16], w1[16], w2[16];
    {
        const ulonglong2* r0 = (const ulonglong2*)(Whh + (size_t)(eg)       * 256 + c * 32);
        const ulonglong2* r1 = (const ulonglong2*)(Whh + (size_t)(256 + eg) * 256 + c * 32);
        const ulonglong2* r2 = (const ulonglong2*)(Whh + (size_t)(512 + eg) * 256 + c * 32);
#pragma unroll
        for (int q = 0; q < 8; q++) {
            ulonglong2 a = r0[q]; w0[2*q] = a.x; w0[2*q+1] = a.y;
            ulonglong2 b = r1[q]; w1[2*q] = b.x; w1[2*q+1] = b.y;
            ulonglong2 d = r2[q]; w2[2*q] = d.x; w2[2*q+1] = d.y;
        }
    }

    const bool is_epi = (c == 0);
    float bn = is_epi ? __ldg(bhh + 512 + eg) : 0.f;

    float ir = 0.f, iz = 0.f, inn = 0.f;
    if (is_epi) {
        const float* gib = g_gi + (size_t)n * 768 + eg;   // t = 0
        ir = __ldg(gib); iz = __ldg(gib + 256); inn = __ldg(gib + 512);
    }

    // pre-mapa peer addresses (owner threads): hbuf[0][eg] and mbar[0] per rank
    unsigned dstH[8], dstM[8];
    if (is_epi) {
        unsigned hl = smem_u32_(&hbuf[0][eg]);
        unsigned ml = smem_u32_(&mbar[0]);
#pragma unroll
        for (int p = 0; p < 8; p++) {
            asm("mapa.shared::cluster.u32 %0, %1, %2;" : "=r"(dstH[p]) : "r"(hl), "r"((unsigned)p));
            asm("mapa.shared::cluster.u32 %0, %1, %2;" : "=r"(dstM[p]) : "r"(ml), "r"((unsigned)p));
        }
    }
    const unsigned mloc = smem_u32_(&mbar[0]);

    asm volatile("barrier.cluster.wait.aligned;" ::: "memory");  // init visible

    for (int t = 0; t < 300; t++) {
        const ulonglong2* hb = (const ulonglong2*)(&hbuf[t & 1][c * 32]);
        unsigned long long a0 = 0ULL, a1 = 0ULL, a2 = 0ULL;
#pragma unroll
        for (int q = 0; q < 8; q++) {
            ulonglong2 h2 = hb[q];
            a0 = fma2_(w0[2*q],   h2.x, a0);
            a1 = fma2_(w1[2*q],   h2.x, a1);
            a2 = fma2_(w2[2*q],   h2.x, a2);
            a0 = fma2_(w0[2*q+1], h2.y, a0);
            a1 = fma2_(w1[2*q+1], h2.y, a1);
            a2 = fma2_(w2[2*q+1], h2.y, a2);
        }
        float s0, s1, s2;
        {
            float lo, hi;
            asm("mov.b64 {%0,%1}, %2;" : "=f"(lo), "=f"(hi) : "l"(a0)); s0 = lo + hi;
            asm("mov.b64 {%0,%1}, %2;" : "=f"(lo), "=f"(hi) : "l"(a1)); s1 = lo + hi;
            asm("mov.b64 {%0,%1}, %2;" : "=f"(lo), "=f"(hi) : "l"(a2)); s2 = lo + hi;
        }
#pragma unroll
        for (int o = 4; o >= 1; o >>= 1) {
            s0 += __shfl_xor_sync(0xffffffffu, s0, o);
            s1 += __shfl_xor_sync(0xffffffffu, s1, o);
            s2 += __shfl_xor_sync(0xffffffffu, s2, o);
        }

        float hnew = 0.f;
        if (is_epi) {
            float rg = sigmoidf_(ir + s0);
            float zg = sigmoidf_(iz + s1);
            float ng = tanhf_(fmaf(rg, s2 + bn, inn));   // n = tanh(i_n + r*(hdot+bhh_n))
            float hold = hbuf[t & 1][eg];
            hnew = fmaf(zg, hold - ng, ng);
        }
        if (t == 299) {
            if (is_epi) {
                outp[(size_t)(n * 300 + t) * 256 + eg] = hnew;
                hid[n * 256 + eg] = hnew;
            }
            break;
        }

        const unsigned boff = (unsigned)(((t + 1) & 1) * 1024);
        const unsigned moff = (unsigned)(((t + 1) & 1) * 8);

        if (tid == 0) {   // arm local barrier for b_{t+1}: 8 CTAs * 128B = 1024B
            asm volatile("mbarrier.arrive.expect_tx.shared.b64 _, [%0], 1024;"
                         :: "r"(mloc + moff) : "memory");
        }
        if (is_epi) {     // push hnew to every CTA's hbuf[next][eg] + signal
            unsigned hbits = __float_as_uint(hnew);
#pragma unroll
            for (int p = 0; p < 8; p++) {
                asm volatile(
                    "st.async.shared::cluster.mbarrier::complete_tx::bytes.b32 [%0], %1, [%2];"
                    :: "r"(dstH[p] + boff), "r"(hbits), "r"(dstM[p] + moff)
                    : "memory");
            }
            outp[(size_t)(n * 300 + t) * 256 + eg] = hnew;
            // prefetch next step's input gates (hides under the wait)
            const float* gib = g_gi + (size_t)((t + 1) * 8 + n) * 768 + eg;
            ir = __ldg(gib); iz = __ldg(gib + 256); inn = __ldg(gib + 512);
        }

        // wait for b_{t+1} on LOCAL mbarrier; parity = (t>>1)&1
        {
            unsigned mb = mloc + moff;
            unsigned par = (unsigned)((t >> 1) & 1);
            unsigned done;
            asm volatile(
                "{\n\t.reg .pred p;\n\t"
                "mbarrier.try_wait.parity.acquire.cta.shared::cta.b64 p, [%1], %2;\n\t"
                "selp.b32 %0, 1, 0, p;\n\t}"
                : "=r"(done) : "r"(mb), "r"(par) : "memory");
            if (!done) {
                asm volatile(
                    "{\n\t.reg .pred P1;\n\t"
                    "W_%=:\n\t"
                    "mbarrier.try_wait.parity.acquire.cta.shared::cta.b64 P1, [%0], %1, 0x989680;\n\t"
                    "@P1 bra.uni D_%=;\n\t"
                    "bra.uni W_%=;\n\t"
                    "D_%=:\n\t}"
                    :: "r"(mb), "r"(par) : "memory");
            }
        }
    }
}

// ---------------- attention: scores + softmax -------------------------------
__global__ void attn_kernel(const float* __restrict__ v, float* __restrict__ attn) {
    __shared__ float w2s[10 * 256];
    __shared__ float vs[256];
    __shared__ float red[8];

    int x = threadIdx.x;                 // 0..159
    int tb = blockIdx.x, n = blockIdx.y;
    int t0 = tb * 10;

    for (int i = x; i < 2560; i += 160)
        w2s[i] = g_w2[(size_t)(n * 300 + t0) * 256 + i];
    for (int i = x; i < 256; i += 160)
        vs[i] = v[i];
    __syncthreads();

    float S;
    {
        float s0 = 0.f, s1 = 0.f, s2 = 0.f, s3 = 0.f;
        for (int e = 0; e < 256; e += 4) {
            s0 += vs[e]; s1 += vs[e + 1]; s2 += vs[e + 2]; s3 += vs[e + 3];
        }
        S = (s0 + s1) + (s2 + s3);
    }

    float acc[10];
#pragma unroll
    for (int tt = 0; tt < 10; tt++) acc[tt] = 0.f;

    const float4* urow = (const float4*)(g_u2 + (size_t)(n * 160 + x) * 256);
    for (int e4 = 0; e4 < 64; e4++) {
        float4 u4 = __ldg(urow + e4);
#pragma unroll
        for (int j = 0; j < 4; j++) {
            float ue = (j == 0) ? u4.x : (j == 1) ? u4.y : (j == 2) ? u4.z : u4.w;
            int e = e4 * 4 + j;
            float ve = vs[e];
#pragma unroll
            for (int tt = 0; tt < 10; tt++) {
                float a = w2s[tt * 256 + e] + ue;      // already * 2*log2e
                float r = rcpf_(1.f + ex2f_(a));       // tanh = 1 - 2r
                acc[tt] = fmaf(ve, r, acc[tt]);
            }
        }
    }

    int lane = x & 31, wid = x >> 5;
    for (int tt = 0; tt < 10; tt++) {
        float sc = fmaf(-2.f, acc[tt], S);
        float m = sc;
#pragma unroll
        for (int o = 16; o > 0; o >>= 1)
            m = fmaxf(m, __shfl_xor_sync(0xffffffffu, m, o));
        if (lane == 0) red[wid] = m;
        __syncthreads();
        m = fmaxf(fmaxf(fmaxf(red[0], red[1]), fmaxf(red[2], red[3])), red[4]);

        float p = ex2f_((sc - m) * LOG2E);
        float s = p;
#pragma unroll
        for (int o = 16; o > 0; o >>= 1)
            s += __shfl_xor_sync(0xffffffffu, s, o);
        __syncthreads();
        if (lane == 0) red[wid] = s;
        __syncthreads();
        s = ((red[0] + red[1]) + (red[2] + red[3])) + red[4];

        attn[(size_t)(n * 300 + t0 + tt) * 160 + x] = p * rcpf_(s);
        __syncthreads();
    }
}

// ---------------- launcher ---------------------------------------------------
extern "C" void kernel_launch(void* const* d_in, const int* in_sizes, int n_in,
                              void* d_out, int out_size) {
    (void)in_sizes; (void)n_in; (void)out_size;
    const float* inputs = (const float*)d_in[0];
    const float* memory = (const float*)d_in[1];
    const float* h0     = (const float*)d_in[2];
    const float* Wih    = (const float*)d_in[3];
    const float* Whh    = (const float*)d_in[4];
    const float* bih    = (const float*)d_in[5];
    const float* bhh    = (const float*)d_in[6];
    const float* W      = (const float*)d_in[7];
    const float* U      = (const float*)d_in[8];
    const float* v      = (const float*)d_in[9];

    float* out     = (float*)d_out;
    float* attn    = out;                 // [8,300,160] = 384000
    float* outputs = out + 384000;        // [8,300,256] = 614400
    float* hidden  = out + 998400;        // [1,8,256]   = 2048

    gi_kernel<<<dim3(150, 3), 256>>>(inputs, Wih, bih, bhh);
    u_kernel<<<80, 256>>>(memory, U);
    gru_kernel<<<64, 256>>>(h0, Whh, bhh, outputs, hidden);
    w_kernel<<<150, 256>>>(outputs, W);
    attn_kernel<<<dim3(30, 8), 160>>>(v, attn);
}